// round 10
// baseline (speedup 1.0000x reference)
#include <cuda_runtime.h>
#include <cuda_fp16.h>

// ===================== problem constants =====================
#define KDIM    256            // c*64+d
#define NDIM    512            // t*32+o
#define MTILE   128
#define NTILE   256            // per-CTA N half
#define THREADS 512
#define KC      64             // K chunk
#define NCHUNK  4

// ===================== device scratch =====================
__device__ __half g_w2h[NDIM * KDIM];   // fused W2 = Wm x Wg, fp16
__device__ float  g_beff[NDIM];

// ===================== smem layout =====================
#define PITCH   144                     // 64 fp16 (128B) + 16B pad: conflict-free (validated)
#define BPLANE  (NTILE * PITCH)         // 36864 per K-chunk plane of B
#define ACH     (MTILE * PITCH)         // 18432 per A chunk buffer
#define SM_B    0                       // 4 planes resident: 147456
#define SM_A    (4 * BPLANE)            // 2 buffers: 36864
#define SM_BEFF (SM_A + 2 * ACH)        // 184320
#define SMEM_TOTAL (SM_BEFF + NTILE * 4)   // 185344 (<227KB, 1 CTA/SM)

// ===================== PTX helpers (validated mappings) =====================
__device__ __forceinline__ unsigned smem_u32(const void* p) {
    unsigned a;
    asm("{ .reg .u64 t; cvta.to.shared.u64 t, %1; cvt.u32.u64 %0, t; }" : "=r"(a) : "l"(p));
    return a;
}
__device__ __forceinline__ void ldmx4(unsigned* r, unsigned addr) {
    asm volatile("ldmatrix.sync.aligned.m8n8.x4.shared.b16 {%0,%1,%2,%3}, [%4];"
                 : "=r"(r[0]), "=r"(r[1]), "=r"(r[2]), "=r"(r[3]) : "r"(addr));
}
__device__ __forceinline__ void mma16816(float* d, const unsigned* a, const unsigned* b) {
    asm volatile("mma.sync.aligned.m16n8k16.row.col.f32.f16.f16.f32 "
                 "{%0,%1,%2,%3}, {%4,%5,%6,%7}, {%8,%9}, {%0,%1,%2,%3};"
                 : "+f"(d[0]), "+f"(d[1]), "+f"(d[2]), "+f"(d[3])
                 : "r"(a[0]), "r"(a[1]), "r"(a[2]), "r"(a[3]), "r"(b[0]), "r"(b[1]));
}
__device__ __forceinline__ void stcs2(float* p, float a, float b) {
    asm volatile("st.global.cs.v2.f32 [%0], {%1, %2};" :: "l"(p), "f"(a), "f"(b) : "memory");
}

// ===================== prep: fused W2 fp16 + effective bias =====================
__global__ void prep_kernel(const float* __restrict__ Wg, const float* __restrict__ bg,
                            const float* __restrict__ Wm) {
    int e = blockIdx.x * blockDim.x + threadIdx.x;
    if (e < NDIM * KDIM) {
        int n = e >> 8, k = e & 255;
        int t = n >> 5, o = n & 31;
        int c = k >> 6, d = k & 63;
        g_w2h[e] = __float2half_rn(Wm[t * 4 + c] * Wg[(t * 32 + o) * 64 + d]);
    }
    if (e < NDIM) {
        int t = e >> 5;
        float s = Wm[t * 4] + Wm[t * 4 + 1] + Wm[t * 4 + 2] + Wm[t * 4 + 3];
        g_beff[e] = s * bg[e];
    }
}

// ===================== persistent fused GEMM: out = relu(Xh @ W2h^T + beff) ==========
__global__ __launch_bounds__(THREADS, 1)
void gemm_kernel(const float* __restrict__ x, float* __restrict__ out,
                 int ntm, int mstride) {
    extern __shared__ char smem[];
    const unsigned sb = smem_u32(smem);
    const int tid = threadIdx.x, wid = tid >> 5, l = tid & 31;
    const int ntl = blockIdx.x & 1;           // fixed N half per CTA
    int       mt  = blockIdx.x >> 1;          // starting M tile
    const int wm  = wid & 3;                  // 32 rows per warp
    const int wn  = wid >> 2;                 // 64 cols per warp

    // ---- one-time: stage resident B (fp16, 4 K-chunk planes) + beff ----
    #pragma unroll
    for (int i = 0; i < 16; i++) {
        int u = tid + i * THREADS;            // 8192 uint4: n(256) x kc(4) x j(8)
        int n = u >> 5, r = u & 31;
        int kc = r >> 3, j = r & 7;
        size_t src = ((size_t)(ntl * NTILE + n)) * (KDIM / 8) + kc * 8 + j;
        unsigned off = (unsigned)(kc * BPLANE + n * PITCH + j * 16);
        *(uint4*)(smem + SM_B + off) = ((const uint4*)g_w2h)[src];
    }
    if (tid < NTILE) ((float*)(smem + SM_BEFF))[tid] = g_beff[ntl * NTILE + tid];

    // ---- prologue: LDG chunk 0 of first tile into regs ----
    float4 xr[4];
    if (mt < ntm) {
        #pragma unroll
        for (int i = 0; i < 4; i++) {
            int f4 = tid + i * THREADS;       // 2048 float4: row(128) x k4(16)
            int m = f4 >> 4, k4 = f4 & 15;
            xr[i] = *(const float4*)(x + ((size_t)(mt * MTILE + m)) * KDIM + k4 * 4);
        }
    }

    const unsigned a_lane = sb + SM_A +
        (unsigned)((wm * 32 + (l & 15)) * PITCH + (l >> 4) * 16);
    const unsigned b_lane = sb + SM_B +
        (unsigned)((wn * 64 + (l & 7) + ((l >> 4) & 1) * 8) * PITCH +
                   ((l >> 3) & 1) * 16);
    const float* beffs = (const float*)(smem + SM_BEFF);

    __syncthreads();  // B + beff visible

    int buf = 0;
    while (mt < ntm) {
        float acc[2][8][4];
        #pragma unroll
        for (int i = 0; i < 2; i++)
            #pragma unroll
            for (int j = 0; j < 8; j++)
                #pragma unroll
                for (int q = 0; q < 4; q++) acc[i][j][q] = 0.f;

        #pragma unroll 1
        for (int kc = 0; kc < NCHUNK; kc++) {
            // ---- STS: regs -> A[buf] as fp16 ----
            #pragma unroll
            for (int i = 0; i < 4; i++) {
                int f4 = tid + i * THREADS;
                int m = f4 >> 4, k4 = f4 & 15;
                float4 v = xr[i];
                __half2 h0 = __float22half2_rn(make_float2(v.x, v.y));
                __half2 h1 = __float22half2_rn(make_float2(v.z, v.w));
                *(uint2*)(smem + SM_A + buf * ACH + m * PITCH + k4 * 8) =
                    make_uint2(*(unsigned*)&h0, *(unsigned*)&h1);
            }
            __syncthreads();

            // ---- LDG next chunk (hides under compute) ----
            int nkc = kc + 1, nmt = mt;
            if (nkc == NCHUNK) { nkc = 0; nmt = mt + mstride; }
            if (nmt < ntm) {
                #pragma unroll
                for (int i = 0; i < 4; i++) {
                    int f4 = tid + i * THREADS;
                    int m = f4 >> 4, k4 = f4 & 15;
                    xr[i] = *(const float4*)(x + ((size_t)(nmt * MTILE + m)) * KDIM
                                             + nkc * KC + k4 * 4);
                }
            }

            // ---- compute: 4 k16-steps vs resident B plane kc ----
            const unsigned ab = a_lane + (unsigned)(buf * ACH);
            const unsigned bb = b_lane + (unsigned)(kc * BPLANE);
            #pragma unroll
            for (int ks = 0; ks < 4; ks++) {
                unsigned bh[4][4];
                #pragma unroll
                for (int jj = 0; jj < 4; jj++)
                    ldmx4(bh[jj], bb + (unsigned)(jj * 16 * PITCH + ks * 32));
                #pragma unroll
                for (int mb = 0; mb < 2; mb++) {
                    unsigned ah[4];
                    ldmx4(ah, ab + (unsigned)(mb * 16 * PITCH + ks * 32));
                    #pragma unroll
                    for (int jj = 0; jj < 4; jj++) {
                        mma16816(acc[mb][jj * 2],     ah, bh[jj]);      // n8 tile 2jj
                        mma16816(acc[mb][jj * 2 + 1], ah, bh[jj] + 2);  // n8 tile 2jj+1
                    }
                }
            }
            buf ^= 1;
        }

        // ---- epilogue: bias + relu, streaming stores ----
        #pragma unroll
        for (int mb = 0; mb < 2; mb++) {
            const int r0 = mt * MTILE + wm * 32 + mb * 16 + (l >> 2);
            #pragma unroll
            for (int j = 0; j < 8; j++) {
                int n = wn * 64 + j * 8 + 2 * (l & 3);
                float2 bv = *(const float2*)(beffs + n);
                float* p0 = out + (size_t)r0 * NDIM + ntl * NTILE + n;
                stcs2(p0,
                      fmaxf(acc[mb][j][0] + bv.x, 0.f),
                      fmaxf(acc[mb][j][1] + bv.y, 0.f));
                stcs2(p0 + 8 * NDIM,
                      fmaxf(acc[mb][j][2] + bv.x, 0.f),
                      fmaxf(acc[mb][j][3] + bv.y, 0.f));
            }
        }
        mt += mstride;
    }
}

// ===================== launch =====================
extern "C" void kernel_launch(void* const* d_in, const int* in_sizes, int n_in,
                              void* d_out, int out_size) {
    const float* x  = (const float*)d_in[0];
    const float* Wg = (const float*)d_in[1];
    const float* bg = (const float*)d_in[2];
    const float* Wm = (const float*)d_in[3];
    float* out = (float*)d_out;

    const int B   = in_sizes[0] / KDIM;      // 32768
    const int ntm = B / MTILE;               // 256

    prep_kernel<<<(NDIM * KDIM + 255) / 256, 256>>>(Wg, bg, Wm);

    cudaFuncSetAttribute(gemm_kernel,
                         cudaFuncAttributeMaxDynamicSharedMemorySize, SMEM_TOTAL);

    int dev = 0, sms = 148;
    cudaGetDevice(&dev);
    cudaDeviceGetAttribute(&sms, cudaDevAttrMultiProcessorCount, dev);
    int grid = sms & ~1;                     // even: half the CTAs per N half
    if (grid < 2) grid = 2;
    if (grid > 2 * ntm) grid = 2 * ntm;
    int mstride = grid >> 1;

    gemm_kernel<<<grid, THREADS, SMEM_TOTAL>>>(x, out, ntm, mstride);
}